// round 1
// baseline (speedup 1.0000x reference)
#include <cuda_runtime.h>
#include <math.h>

#define NB   64
#define NPER 256
#define DIN  256
#define DOUT 128
#define EPER 8192
#define MAXE 192
#define ADJ_N 8192
#define ADJ_ELEMS (67108864u)   // 8192*8192

// ---------------- scratch (static device globals; no allocation) ----------------
__device__ float g_agg[NB*NPER*DIN];          // mean-aggregated neighbor feats
__device__ float g_feat[NB*NPER*DOUT];        // sage(W_feat) output
__device__ float g_assign[NB*NPER*DOUT];      // softmax(sage(W_pool))
__device__ float g_AS[NB*NPER*DOUT];          // A @ assign
__device__ unsigned char g_elist[NB*NPER*MAXE]; // per-dst src lists (dup edges kept)
__device__ int   g_ecnt[NB*NPER];
__device__ float g_ideg[NB*NPER];

// ---------------- K1a: build per-dst edge lists + degrees ----------------
__global__ void k_build(const int* __restrict__ esrc, const int* __restrict__ edst) {
    int b = blockIdx.x;
    __shared__ int scnt[NPER];
    for (int i = threadIdx.x; i < NPER; i += blockDim.x) scnt[i] = 0;
    __syncthreads();
    const int* s = esrc + b*EPER;
    const int* d = edst + b*EPER;
    for (int e = threadIdx.x; e < EPER; e += blockDim.x) {
        int dst = d[e];
        int src = s[e];
        int pos = atomicAdd(&scnt[dst], 1);
        if (pos < MAXE) g_elist[(b*NPER + dst)*MAXE + pos] = (unsigned char)src;
    }
    __syncthreads();
    for (int i = threadIdx.x; i < NPER; i += blockDim.x) {
        int c = scnt[i];
        g_ecnt[b*NPER + i] = c;
        g_ideg[b*NPER + i] = 1.0f / (float)(c > 0 ? c : 1);
    }
}

// ---------------- K1b: agg = (sum over in-edges of h[src]) * ideg ----------------
// grid (NB, 2) ; block 128.  warp w handles 64 dsts, lane covers 4 feats (float4).
__global__ void k_agg(const float* __restrict__ h) {
    int b = blockIdx.x, half = blockIdx.y;
    int w = threadIdx.x >> 5, l = threadIdx.x & 31;
    const float4* hb = (const float4*)(h + (size_t)b*NPER*DIN);
    int f4 = half*32 + l;   // float4 index within 64-float4 row
    int d0 = w * 64;
    for (int dst = d0; dst < d0 + 64; dst++) {
        int nn = g_ecnt[b*NPER + dst]; if (nn > MAXE) nn = MAXE;
        float ideg = g_ideg[b*NPER + dst];
        const unsigned char* lst = &g_elist[(b*NPER + dst)*MAXE];
        float4 acc = make_float4(0.f,0.f,0.f,0.f);
        for (int j = 0; j < nn; j++) {
            int src = lst[j];
            float4 v = hb[src*64 + f4];
            acc.x += v.x; acc.y += v.y; acc.z += v.z; acc.w += v.w;
        }
        acc.x *= ideg; acc.y *= ideg; acc.z *= ideg; acc.w *= ideg;
        ((float4*)(g_agg + (size_t)(b*NPER + dst)*DIN))[f4] = acc;
    }
}

// ---------------- K2: Z = [h|agg] @ [W_feat | W_pool] + b, then epilogue ----------------
// grid (NB, 8) row tiles of 32; block 256 (thread = output column 0..255).
__global__ void k_gemm(const float* __restrict__ h,
                       const float* __restrict__ Wf, const float* __restrict__ bf,
                       const float* __restrict__ Wp, const float* __restrict__ bp) {
    extern __shared__ float Xs[];   // 32*512 floats = 64KB, reused as Zs[32*256]
    int b = blockIdx.x, r0 = blockIdx.y * 32;
    int t = threadIdx.x;

    for (int idx = t; idx < 32*512; idx += 256) {
        int r = idx >> 9, k = idx & 511;
        float v;
        if (k < 256) v = h[(size_t)(b*NPER + r0 + r)*DIN + k];
        else         v = g_agg[(size_t)(b*NPER + r0 + r)*DIN + (k - 256)];
        Xs[idx] = v;
    }
    __syncthreads();

    const float* Wcol = (t < 128) ? (Wf + t) : (Wp + (t - 128));
    float acc[32];
    #pragma unroll
    for (int r = 0; r < 32; r++) acc[r] = 0.f;

    for (int k = 0; k < 512; k += 4) {
        float w0 = Wcol[(k+0)*128];
        float w1 = Wcol[(k+1)*128];
        float w2 = Wcol[(k+2)*128];
        float w3 = Wcol[(k+3)*128];
        int k4 = k >> 2;
        #pragma unroll
        for (int r = 0; r < 32; r++) {
            float4 x = ((const float4*)Xs)[r*128 + k4];
            acc[r] = fmaf(x.x, w0, acc[r]);
            acc[r] = fmaf(x.y, w1, acc[r]);
            acc[r] = fmaf(x.z, w2, acc[r]);
            acc[r] = fmaf(x.w, w3, acc[r]);
        }
    }
    float bias = (t < 128) ? bf[t] : bp[t - 128];
    #pragma unroll
    for (int r = 0; r < 32; r++) acc[r] += bias;

    __syncthreads();
    #pragma unroll
    for (int r = 0; r < 32; r++) Xs[r*256 + t] = acc[r];
    __syncthreads();

    // epilogue: warp w handles rows w*4..w*4+3
    int w = t >> 5, l = t & 31;
    for (int rr = 0; rr < 4; rr++) {
        int r = w*4 + rr;
        float f0 = Xs[r*256 + l +  0], f1 = Xs[r*256 + l + 32];
        float f2 = Xs[r*256 + l + 64], f3 = Xs[r*256 + l + 96];
        float p0 = Xs[r*256 + 128 + l +  0], p1 = Xs[r*256 + 128 + l + 32];
        float p2 = Xs[r*256 + 128 + l + 64], p3 = Xs[r*256 + 128 + l + 96];

        float ssf = f0*f0 + f1*f1 + f2*f2 + f3*f3;
        float ssp = p0*p0 + p1*p1 + p2*p2 + p3*p3;
        #pragma unroll
        for (int o = 16; o > 0; o >>= 1) {
            ssf += __shfl_xor_sync(0xffffffffu, ssf, o);
            ssp += __shfl_xor_sync(0xffffffffu, ssp, o);
        }
        float invf = rsqrtf(fmaxf(ssf, 1e-24f));
        float invp = rsqrtf(fmaxf(ssp, 1e-24f));

        f0 = fmaxf(f0*invf, 0.f); f1 = fmaxf(f1*invf, 0.f);
        f2 = fmaxf(f2*invf, 0.f); f3 = fmaxf(f3*invf, 0.f);
        p0 = fmaxf(p0*invp, 0.f); p1 = fmaxf(p1*invp, 0.f);
        p2 = fmaxf(p2*invp, 0.f); p3 = fmaxf(p3*invp, 0.f);

        // softmax over the 128 pool values
        float m = fmaxf(fmaxf(p0, p1), fmaxf(p2, p3));
        #pragma unroll
        for (int o = 16; o > 0; o >>= 1) m = fmaxf(m, __shfl_xor_sync(0xffffffffu, m, o));
        float e0 = __expf(p0 - m), e1 = __expf(p1 - m);
        float e2 = __expf(p2 - m), e3 = __expf(p3 - m);
        float s = e0 + e1 + e2 + e3;
        #pragma unroll
        for (int o = 16; o > 0; o >>= 1) s += __shfl_xor_sync(0xffffffffu, s, o);
        float isum = 1.0f / s;

        size_t grow = (size_t)(b*NPER + r0 + r)*DOUT;
        g_feat[grow + l +  0] = f0; g_feat[grow + l + 32] = f1;
        g_feat[grow + l + 64] = f2; g_feat[grow + l + 96] = f3;
        g_assign[grow + l +  0] = e0*isum; g_assign[grow + l + 32] = e1*isum;
        g_assign[grow + l + 64] = e2*isum; g_assign[grow + l + 96] = e3*isum;
    }
}

// ---------------- K4: AS[i,:] = sum over in-edges of assign[src,:] ----------------
// grid (NB, 2); block 128. assign graph cached in smem (128KB).
__global__ void k_as() {
    extern __shared__ float4 Ss[];   // 256*32 float4
    int b = blockIdx.x, dh = blockIdx.y;
    const float4* Sg = (const float4*)(g_assign + (size_t)b*NPER*DOUT);
    for (int idx = threadIdx.x; idx < 256*32; idx += 128) Ss[idx] = Sg[idx];
    __syncthreads();
    int w = threadIdx.x >> 5, l = threadIdx.x & 31;
    for (int i = 0; i < 32; i++) {
        int dst = dh*128 + w*32 + i;
        int nn = g_ecnt[b*NPER + dst]; if (nn > MAXE) nn = MAXE;
        const unsigned char* lst = &g_elist[(b*NPER + dst)*MAXE];
        float4 acc = make_float4(0.f,0.f,0.f,0.f);
        for (int j = 0; j < nn; j++) {
            float4 v = Ss[lst[j]*32 + l];
            acc.x += v.x; acc.y += v.y; acc.z += v.z; acc.w += v.w;
        }
        ((float4*)(g_AS + (size_t)(b*NPER + dst)*DOUT))[l] = acc;
    }
}

// ---------------- K5: out = S^T @ X ; which=0 -> h_pool(F), which=1 -> blocks(AS) ----
// grid (NB, 2); block 256 = 16x16, each thread 8x8 outputs.
__global__ void k_pool(float* __restrict__ out) {
    extern __shared__ float sm[];           // Ss 64*128 + Xs 64*128 = 64KB
    float* Ssm = sm;
    float* Xsm = sm + 64*128;
    int b = blockIdx.x, which = blockIdx.y;
    const float* Sg = g_assign + (size_t)b*NPER*DOUT;
    const float* Xg = (which ? g_AS : g_feat) + (size_t)b*NPER*DOUT;

    float acc[8][8];
    #pragma unroll
    for (int i = 0; i < 8; i++)
        #pragma unroll
        for (int j = 0; j < 8; j++) acc[i][j] = 0.f;

    int tk = threadIdx.x >> 4, td = threadIdx.x & 15;

    for (int c = 0; c < NPER; c += 64) {
        for (int idx = threadIdx.x; idx < 64*128; idx += 256) {
            Ssm[idx] = Sg[c*128 + idx];
            Xsm[idx] = Xg[c*128 + idx];
        }
        __syncthreads();
        for (int n = 0; n < 64; n++) {
            float4 a0 = ((const float4*)(Ssm + n*128))[tk*2];
            float4 a1 = ((const float4*)(Ssm + n*128))[tk*2 + 1];
            float4 x0 = ((const float4*)(Xsm + n*128))[td*2];
            float4 x1 = ((const float4*)(Xsm + n*128))[td*2 + 1];
            float a[8] = {a0.x,a0.y,a0.z,a0.w,a1.x,a1.y,a1.z,a1.w};
            float x[8] = {x0.x,x0.y,x0.z,x0.w,x1.x,x1.y,x1.z,x1.w};
            #pragma unroll
            for (int i = 0; i < 8; i++)
                #pragma unroll
                for (int j = 0; j < 8; j++)
                    acc[i][j] = fmaf(a[i], x[j], acc[i][j]);
        }
        __syncthreads();
    }

    if (which == 0) {
        // h_pool region starts after adj
        #pragma unroll
        for (int i = 0; i < 8; i++) {
            size_t row = (size_t)b*128 + tk*8 + i;
            size_t base = (size_t)ADJ_ELEMS + row*DOUT + td*8;
            #pragma unroll
            for (int j = 0; j < 8; j++) out[base + j] = acc[i][j];
        }
    } else {
        #pragma unroll
        for (int i = 0; i < 8; i++) {
            size_t row = (size_t)b*128 + tk*8 + i;
            size_t base = row*ADJ_N + (size_t)b*128 + td*8;
            #pragma unroll
            for (int j = 0; j < 8; j++) out[base + j] = acc[i][j];
        }
    }
}

// ---------------- launch ----------------
extern "C" void kernel_launch(void* const* d_in, const int* in_sizes, int n_in,
                              void* d_out, int out_size) {
    const float* h    = (const float*)d_in[0];
    const int*   esrc = (const int*)d_in[1];
    const int*   edst = (const int*)d_in[2];
    const float* Wf   = (const float*)d_in[3];
    const float* bf   = (const float*)d_in[4];
    const float* Wp   = (const float*)d_in[5];
    const float* bp   = (const float*)d_in[6];
    float* out = (float*)d_out;

    cudaFuncSetAttribute(k_gemm, cudaFuncAttributeMaxDynamicSharedMemorySize, 65536);
    cudaFuncSetAttribute(k_as,   cudaFuncAttributeMaxDynamicSharedMemorySize, 131072);
    cudaFuncSetAttribute(k_pool, cudaFuncAttributeMaxDynamicSharedMemorySize, 65536);

    // zero the (mostly block-diagonal-sparse) adjacency output
    cudaMemsetAsync(d_out, 0, (size_t)ADJ_ELEMS * sizeof(float));

    k_build<<<NB, 256>>>(esrc, edst);
    k_agg<<<dim3(NB, 2), 128>>>(h);
    k_gemm<<<dim3(NB, 8), 256, 65536>>>(h, Wf, bf, Wp, bp);
    k_as<<<dim3(NB, 2), 128, 131072>>>();
    k_pool<<<dim3(NB, 2), 256, 65536>>>(out);
}

// round 2
// speedup vs baseline: 1.1308x; 1.1308x over previous
#include <cuda_runtime.h>
#include <math.h>

#define NB   64
#define NPER 256
#define DIN  256
#define DOUT 128
#define EPER 8192
#define MAXE 192
#define ADJ_N 8192
#define ADJ_ELEMS (67108864u)   // 8192*8192

// ---------------- scratch (static device globals; no allocation) ----------------
__device__ float g_agg[NB*NPER*DIN];            // mean-aggregated neighbor feats
__device__ float g_feat[NB*NPER*DOUT];          // sage(W_feat) output
__device__ float g_assign[NB*NPER*DOUT];        // softmax(sage(W_pool))
__device__ float g_AS[NB*NPER*DOUT];            // A @ assign
__device__ unsigned char g_elist[NB*NPER*MAXE]; // per-dst src lists
__device__ int   g_ecnt[NB*NPER];
__device__ float g_ideg[NB*NPER];

// ---------------- f32x2 helpers ----------------
__device__ __forceinline__ unsigned long long fma2(unsigned long long a,
                                                   unsigned long long b,
                                                   unsigned long long c) {
    unsigned long long d;
    asm("fma.rn.f32x2 %0, %1, %2, %3;" : "=l"(d) : "l"(a), "l"(b), "l"(c));
    return d;
}
__device__ __forceinline__ unsigned long long dup2(float w) {
    unsigned long long d;
    asm("mov.b64 %0, {%1, %1};" : "=l"(d) : "f"(w));
    return d;
}
__device__ __forceinline__ void unpack2(unsigned long long v, float& lo, float& hi) {
    asm("mov.b64 {%0, %1}, %2;" : "=f"(lo), "=f"(hi) : "l"(v));
}

// ---------------- K1a: build per-dst edge lists + degrees ----------------
__global__ void k_build(const int* __restrict__ esrc, const int* __restrict__ edst) {
    int b = blockIdx.x;
    __shared__ int scnt[NPER];
    for (int i = threadIdx.x; i < NPER; i += blockDim.x) scnt[i] = 0;
    __syncthreads();
    const int* s = esrc + b*EPER;
    const int* d = edst + b*EPER;
    for (int e = threadIdx.x; e < EPER; e += blockDim.x) {
        int dst = d[e];
        int src = s[e];
        int pos = atomicAdd(&scnt[dst], 1);
        if (pos < MAXE) g_elist[(b*NPER + dst)*MAXE + pos] = (unsigned char)src;
    }
    __syncthreads();
    for (int i = threadIdx.x; i < NPER; i += blockDim.x) {
        int c = scnt[i];
        g_ecnt[b*NPER + i] = c;
        g_ideg[b*NPER + i] = 1.0f / (float)(c > 0 ? c : 1);
    }
}

// ---------------- K1b: agg = (sum over in-edges of h[src]) * ideg --------------
// grid (NB, fh=2, dh=2); block 256; smem = 256 nodes x 128 feats = 128KB
__global__ void k_agg(const float* __restrict__ h) {
    extern __shared__ float hs[];   // 256*128
    int b = blockIdx.x, fh = blockIdx.y, dh = blockIdx.z;
    int t = threadIdx.x;
    const float* hb = h + (size_t)b*NPER*DIN + fh*128;
    for (int idx = t; idx < 256*128; idx += 256) {
        int node = idx >> 7, f = idx & 127;
        hs[idx] = hb[node*DIN + f];
    }
    __syncthreads();
    const float4* hs4 = (const float4*)hs;
    int w = t >> 5, l = t & 31;
    for (int ii = 0; ii < 16; ii++) {
        int dst = dh*128 + w*16 + ii;
        int gi = b*NPER + dst;
        int nn = g_ecnt[gi]; if (nn > MAXE) nn = MAXE;
        float ideg = g_ideg[gi];
        const unsigned char* lst = &g_elist[(size_t)gi*MAXE];
        float4 acc = make_float4(0.f,0.f,0.f,0.f);
        int j = 0;
        for (; j + 4 <= nn; j += 4) {
            uchar4 s4 = *(const uchar4*)(lst + j);
            float4 v0 = hs4[s4.x*32 + l];
            float4 v1 = hs4[s4.y*32 + l];
            float4 v2 = hs4[s4.z*32 + l];
            float4 v3 = hs4[s4.w*32 + l];
            acc.x += (v0.x + v1.x) + (v2.x + v3.x);
            acc.y += (v0.y + v1.y) + (v2.y + v3.y);
            acc.z += (v0.z + v1.z) + (v2.z + v3.z);
            acc.w += (v0.w + v1.w) + (v2.w + v3.w);
        }
        for (; j < nn; j++) {
            float4 v = hs4[lst[j]*32 + l];
            acc.x += v.x; acc.y += v.y; acc.z += v.z; acc.w += v.w;
        }
        acc.x *= ideg; acc.y *= ideg; acc.z *= ideg; acc.w *= ideg;
        ((float4*)g_agg)[(size_t)gi*64 + fh*32 + l] = acc;
    }
}

// ---------------- K2: Z = [h|agg] @ [W_feat | W_pool] + b, epilogue ----------------
// grid (NB, 8) row tiles of 32; block 256 (thread = output col 0..255).
// X staged in smem as f32x2 row-pairs: pair p (rows 2p,2p+1), Xs[p*1024 + k*2 + parity]
__global__ void __launch_bounds__(256) k_gemm(
        const float* __restrict__ h,
        const float* __restrict__ Wf, const float* __restrict__ bf,
        const float* __restrict__ Wp, const float* __restrict__ bp) {
    extern __shared__ float Xs[];   // 16*1024 floats = 64KB, reused as Zs[32*256]
    int b = blockIdx.x, r0 = blockIdx.y * 32;
    int t = threadIdx.x;

    for (int idx = t; idx < 32*512; idx += 256) {
        int r = idx >> 9, k = idx & 511;
        float v;
        if (k < 256) v = h[(size_t)(b*NPER + r0 + r)*DIN + k];
        else         v = g_agg[(size_t)(b*NPER + r0 + r)*DIN + (k - 256)];
        Xs[(r >> 1)*1024 + k*2 + (r & 1)] = v;
    }
    __syncthreads();

    const float* Wcol = (t < 128) ? (Wf + t) : (Wp + (t - 128));
    unsigned long long acc[16];
    #pragma unroll
    for (int p = 0; p < 16; p++) acc[p] = 0ull;

    const ulonglong2* Xp = (const ulonglong2*)Xs;   // elem = 2 consecutive k of a pair
    for (int k0 = 0; k0 < 512; k0 += 4) {
        float w0 = Wcol[(k0+0)*128];
        float w1 = Wcol[(k0+1)*128];
        float w2 = Wcol[(k0+2)*128];
        float w3 = Wcol[(k0+3)*128];
        unsigned long long W0 = dup2(w0), W1 = dup2(w1), W2 = dup2(w2), W3 = dup2(w3);
        int kb = k0 >> 1;
        #pragma unroll
        for (int p = 0; p < 16; p++) {
            ulonglong2 X0 = Xp[p*256 + kb];       // k0, k0+1
            ulonglong2 X1 = Xp[p*256 + kb + 1];   // k0+2, k0+3
            acc[p] = fma2(X0.x, W0, acc[p]);
            acc[p] = fma2(X0.y, W1, acc[p]);
            acc[p] = fma2(X1.x, W2, acc[p]);
            acc[p] = fma2(X1.y, W3, acc[p]);
        }
    }

    float bias = (t < 128) ? bf[t] : bp[t - 128];
    __syncthreads();   // all reads of Xs done before reuse as Zs
    #pragma unroll
    for (int p = 0; p < 16; p++) {
        float lo, hi;
        unpack2(acc[p], lo, hi);
        Xs[(2*p    )*256 + t] = lo + bias;
        Xs[(2*p + 1)*256 + t] = hi + bias;
    }
    __syncthreads();

    // epilogue: warp w handles rows w*4..w*4+3
    int w = t >> 5, l = t & 31;
    for (int rr = 0; rr < 4; rr++) {
        int r = w*4 + rr;
        float f0 = Xs[r*256 + l +  0], f1 = Xs[r*256 + l + 32];
        float f2 = Xs[r*256 + l + 64], f3 = Xs[r*256 + l + 96];
        float p0 = Xs[r*256 + 128 + l +  0], p1 = Xs[r*256 + 128 + l + 32];
        float p2 = Xs[r*256 + 128 + l + 64], p3 = Xs[r*256 + 128 + l + 96];

        float ssf = f0*f0 + f1*f1 + f2*f2 + f3*f3;
        float ssp = p0*p0 + p1*p1 + p2*p2 + p3*p3;
        #pragma unroll
        for (int o = 16; o > 0; o >>= 1) {
            ssf += __shfl_xor_sync(0xffffffffu, ssf, o);
            ssp += __shfl_xor_sync(0xffffffffu, ssp, o);
        }
        float invf = rsqrtf(fmaxf(ssf, 1e-24f));
        float invp = rsqrtf(fmaxf(ssp, 1e-24f));

        f0 = fmaxf(f0*invf, 0.f); f1 = fmaxf(f1*invf, 0.f);
        f2 = fmaxf(f2*invf, 0.f); f3 = fmaxf(f3*invf, 0.f);
        p0 = fmaxf(p0*invp, 0.f); p1 = fmaxf(p1*invp, 0.f);
        p2 = fmaxf(p2*invp, 0.f); p3 = fmaxf(p3*invp, 0.f);

        float m = fmaxf(fmaxf(p0, p1), fmaxf(p2, p3));
        #pragma unroll
        for (int o = 16; o > 0; o >>= 1) m = fmaxf(m, __shfl_xor_sync(0xffffffffu, m, o));
        float e0 = __expf(p0 - m), e1 = __expf(p1 - m);
        float e2 = __expf(p2 - m), e3 = __expf(p3 - m);
        float s = e0 + e1 + e2 + e3;
        #pragma unroll
        for (int o = 16; o > 0; o >>= 1) s += __shfl_xor_sync(0xffffffffu, s, o);
        float isum = 1.0f / s;

        size_t grow = (size_t)(b*NPER + r0 + r)*DOUT;
        g_feat[grow + l +  0] = f0; g_feat[grow + l + 32] = f1;
        g_feat[grow + l + 64] = f2; g_feat[grow + l + 96] = f3;
        g_assign[grow + l +  0] = e0*isum; g_assign[grow + l + 32] = e1*isum;
        g_assign[grow + l + 64] = e2*isum; g_assign[grow + l + 96] = e3*isum;
    }
}

// ---------------- K4: AS[dst,:] = sum over in-edges of assign[src,:] ------------
// grid (NB, 2 dst-halves); block 256; smem = whole assign graph 128KB
__global__ void k_as() {
    extern __shared__ float ss[];   // 256*128
    int b = blockIdx.x, dh = blockIdx.y, t = threadIdx.x;
    const float* Sg = g_assign + (size_t)b*NPER*DOUT;
    for (int idx = t; idx < 256*128; idx += 256) ss[idx] = Sg[idx];
    __syncthreads();
    const float4* ss4 = (const float4*)ss;
    int w = t >> 5, l = t & 31;
    for (int ii = 0; ii < 16; ii++) {
        int dst = dh*128 + w*16 + ii;
        int gi = b*NPER + dst;
        int nn = g_ecnt[gi]; if (nn > MAXE) nn = MAXE;
        const unsigned char* lst = &g_elist[(size_t)gi*MAXE];
        float4 acc = make_float4(0.f,0.f,0.f,0.f);
        int j = 0;
        for (; j + 4 <= nn; j += 4) {
            uchar4 s4 = *(const uchar4*)(lst + j);
            float4 v0 = ss4[s4.x*32 + l];
            float4 v1 = ss4[s4.y*32 + l];
            float4 v2 = ss4[s4.z*32 + l];
            float4 v3 = ss4[s4.w*32 + l];
            acc.x += (v0.x + v1.x) + (v2.x + v3.x);
            acc.y += (v0.y + v1.y) + (v2.y + v3.y);
            acc.z += (v0.z + v1.z) + (v2.z + v3.z);
            acc.w += (v0.w + v1.w) + (v2.w + v3.w);
        }
        for (; j < nn; j++) {
            float4 v = ss4[lst[j]*32 + l];
            acc.x += v.x; acc.y += v.y; acc.z += v.z; acc.w += v.w;
        }
        ((float4*)g_AS)[(size_t)gi*32 + l] = acc;
    }
}

// ---------------- K5: out = S^T @ X ; which=0 -> h_pool(F), which=1 -> blocks(AS)
// grid (NB, 2); block 256 = 16x16; thread computes 8x8 via f32x2 (8x4 packed)
__global__ void k_pool(float* __restrict__ out) {
    extern __shared__ float sm[];           // Ssm 64*128 + Xsm 64*128 = 64KB
    float* Ssm = sm;
    float* Xsm = sm + 64*128;
    int b = blockIdx.x, which = blockIdx.y;
    const float* Sg = g_assign + (size_t)b*NPER*DOUT;
    const float* Xg = (which ? g_AS : g_feat) + (size_t)b*NPER*DOUT;

    unsigned long long acc[8][4];
    #pragma unroll
    for (int i = 0; i < 8; i++)
        #pragma unroll
        for (int j = 0; j < 4; j++) acc[i][j] = 0ull;

    int tk = threadIdx.x >> 4, td = threadIdx.x & 15;

    for (int c = 0; c < NPER; c += 64) {
        const float4* Sg4 = (const float4*)(Sg + c*128);
        const float4* Xg4 = (const float4*)(Xg + c*128);
        for (int idx = threadIdx.x; idx < 64*32; idx += 256) {
            ((float4*)Ssm)[idx] = Sg4[idx];
            ((float4*)Xsm)[idx] = Xg4[idx];
        }
        __syncthreads();
        for (int n = 0; n < 64; n++) {
            float4 a0 = ((const float4*)(Ssm + n*128))[tk*2];
            float4 a1 = ((const float4*)(Ssm + n*128))[tk*2 + 1];
            ulonglong2 x0 = ((const ulonglong2*)(Xsm + n*128))[td*2];
            ulonglong2 x1 = ((const ulonglong2*)(Xsm + n*128))[td*2 + 1];
            unsigned long long A[8] = {
                dup2(a0.x), dup2(a0.y), dup2(a0.z), dup2(a0.w),
                dup2(a1.x), dup2(a1.y), dup2(a1.z), dup2(a1.w)
            };
            #pragma unroll
            for (int i = 0; i < 8; i++) {
                acc[i][0] = fma2(x0.x, A[i], acc[i][0]);
                acc[i][1] = fma2(x0.y, A[i], acc[i][1]);
                acc[i][2] = fma2(x1.x, A[i], acc[i][2]);
                acc[i][3] = fma2(x1.y, A[i], acc[i][3]);
            }
        }
        __syncthreads();
    }

    #pragma unroll
    for (int i = 0; i < 8; i++) {
        size_t row = (size_t)b*128 + tk*8 + i;
        size_t base = which ? (row*ADJ_N + (size_t)b*128 + td*8)
                            : ((size_t)ADJ_ELEMS + row*DOUT + td*8);
        #pragma unroll
        for (int j = 0; j < 4; j++) {
            float lo, hi;
            unpack2(acc[i][j], lo, hi);
            out[base + 2*j]     = lo;
            out[base + 2*j + 1] = hi;
        }
    }
}

// ---------------- launch ----------------
extern "C" void kernel_launch(void* const* d_in, const int* in_sizes, int n_in,
                              void* d_out, int out_size) {
    const float* h    = (const float*)d_in[0];
    const int*   esrc = (const int*)d_in[1];
    const int*   edst = (const int*)d_in[2];
    const float* Wf   = (const float*)d_in[3];
    const float* bf   = (const float*)d_in[4];
    const float* Wp   = (const float*)d_in[5];
    const float* bp   = (const float*)d_in[6];
    float* out = (float*)d_out;

    static cudaStream_t s_side = nullptr;
    static cudaEvent_t  e_fork = nullptr, e_join = nullptr;
    if (!s_side) {
        cudaStreamCreateWithFlags(&s_side, cudaStreamNonBlocking);
        cudaEventCreateWithFlags(&e_fork, cudaEventDisableTiming);
        cudaEventCreateWithFlags(&e_join, cudaEventDisableTiming);
    }

    cudaFuncSetAttribute(k_agg,  cudaFuncAttributeMaxDynamicSharedMemorySize, 131072);
    cudaFuncSetAttribute(k_gemm, cudaFuncAttributeMaxDynamicSharedMemorySize, 65536);
    cudaFuncSetAttribute(k_as,   cudaFuncAttributeMaxDynamicSharedMemorySize, 131072);
    cudaFuncSetAttribute(k_pool, cudaFuncAttributeMaxDynamicSharedMemorySize, 65536);

    // fork: zero the adjacency output on a side stream, overlapped with compute
    cudaEventRecord(e_fork, 0);
    cudaStreamWaitEvent(s_side, e_fork, 0);
    cudaMemsetAsync(d_out, 0, (size_t)ADJ_ELEMS * sizeof(float), s_side);
    cudaEventRecord(e_join, s_side);

    k_build<<<NB, 256>>>(esrc, edst);
    k_agg<<<dim3(NB, 2, 2), 256, 131072>>>(h);
    k_gemm<<<dim3(NB, 8), 256, 65536>>>(h, Wf, bf, Wp, bp);
    k_as<<<dim3(NB, 2), 256, 131072>>>();

    // join: adj must be zeroed before k_pool writes the diagonal blocks
    cudaStreamWaitEvent(0, e_join, 0);
    k_pool<<<dim3(NB, 2), 256, 65536>>>(out);
}

// round 3
// speedup vs baseline: 1.5345x; 1.3570x over previous
#include <cuda_runtime.h>
#include <math.h>

#define NB   64
#define NPER 256
#define DIN  256
#define DOUT 128
#define EPER 8192
#define MAXE 192
#define ADJ_N 8192
#define ADJ_ELEMS (67108864u)   // 8192*8192

// ---------------- scratch ----------------
__device__ float g_agg[NB*NPER*DIN];
__device__ float g_feat[NB*NPER*DOUT];
__device__ float g_assign[NB*NPER*DOUT];
__device__ float g_AS[NB*NPER*DOUT];
__device__ unsigned char g_elist[NB*NPER*MAXE];
__device__ int   g_ecnt[NB*NPER];
__device__ float g_ideg[NB*NPER];

// ---------------- f32x2 helpers ----------------
__device__ __forceinline__ unsigned long long fma2(unsigned long long a,
                                                   unsigned long long b,
                                                   unsigned long long c) {
    unsigned long long d;
    asm("fma.rn.f32x2 %0, %1, %2, %3;" : "=l"(d) : "l"(a), "l"(b), "l"(c));
    return d;
}
__device__ __forceinline__ unsigned long long add2(unsigned long long a,
                                                   unsigned long long b) {
    unsigned long long d;
    asm("add.rn.f32x2 %0, %1, %2;" : "=l"(d) : "l"(a), "l"(b));
    return d;
}
__device__ __forceinline__ unsigned long long dup2(float w) {
    unsigned long long d;
    asm("mov.b64 %0, {%1, %1};" : "=l"(d) : "f"(w));
    return d;
}
__device__ __forceinline__ void unpack2(unsigned long long v, float& lo, float& hi) {
    asm("mov.b64 {%0, %1}, %2;" : "=f"(lo), "=f"(hi) : "l"(v));
}

// ---------------- K1a: per-dst edge lists + degrees ----------------
__global__ void k_build(const int* __restrict__ esrc, const int* __restrict__ edst) {
    int b = blockIdx.x;
    __shared__ int scnt[NPER];
    for (int i = threadIdx.x; i < NPER; i += blockDim.x) scnt[i] = 0;
    __syncthreads();
    const int* s = esrc + b*EPER;
    const int* d = edst + b*EPER;
    for (int e = threadIdx.x; e < EPER; e += blockDim.x) {
        int dst = d[e];
        int src = s[e];
        int pos = atomicAdd(&scnt[dst], 1);
        if (pos < MAXE) g_elist[(b*NPER + dst)*MAXE + pos] = (unsigned char)src;
    }
    __syncthreads();
    for (int i = threadIdx.x; i < NPER; i += blockDim.x) {
        int c = scnt[i];
        g_ecnt[b*NPER + i] = c;
        g_ideg[b*NPER + i] = 1.0f / (float)(c > 0 ? c : 1);
    }
}

// ---------------- K1b: agg = mean of in-neighbor h ----------------
// grid (NB, 2 feat-halves); block 512; smem 128KB (256 nodes x 128 feats)
__global__ void __launch_bounds__(512) k_agg(const float* __restrict__ h) {
    extern __shared__ float hs[];
    int b = blockIdx.x, fh = blockIdx.y, t = threadIdx.x;
    for (int i4 = t; i4 < 256*32; i4 += 512) {
        int node = i4 >> 5, f4 = i4 & 31;
        ((float4*)hs)[i4] = *(const float4*)(h + (size_t)(b*256 + node)*DIN + fh*128 + f4*4);
    }
    __syncthreads();
    const ulonglong2* hsv = (const ulonglong2*)hs;   // idx = node*32 + l
    int w = t >> 5, l = t & 31;
    for (int ii = 0; ii < 16; ii++) {
        int dst = w*16 + ii;
        int gi = b*NPER + dst;
        int nn = g_ecnt[gi]; if (nn > MAXE) nn = MAXE;
        float ideg = g_ideg[gi];
        const unsigned char* lst = &g_elist[(size_t)gi*MAXE];
        unsigned long long a0 = 0, a1 = 0, b0 = 0, b1 = 0;
        int j = 0;
        for (; j + 4 <= nn; j += 4) {
            uchar4 s4 = *(const uchar4*)(lst + j);
            ulonglong2 v0 = hsv[s4.x*32 + l];
            ulonglong2 v1 = hsv[s4.y*32 + l];
            ulonglong2 v2 = hsv[s4.z*32 + l];
            ulonglong2 v3 = hsv[s4.w*32 + l];
            a0 = add2(a0, v0.x); a1 = add2(a1, v0.y);
            b0 = add2(b0, v1.x); b1 = add2(b1, v1.y);
            a0 = add2(a0, v2.x); a1 = add2(a1, v2.y);
            b0 = add2(b0, v3.x); b1 = add2(b1, v3.y);
        }
        for (; j < nn; j++) {
            ulonglong2 v = hsv[lst[j]*32 + l];
            a0 = add2(a0, v.x); a1 = add2(a1, v.y);
        }
        a0 = add2(a0, b0); a1 = add2(a1, b1);
        float x0, x1, x2, x3;
        unpack2(a0, x0, x1); unpack2(a1, x2, x3);
        float4 o = make_float4(x0*ideg, x1*ideg, x2*ideg, x3*ideg);
        *(float4*)(g_agg + (size_t)gi*DIN + fh*128 + l*4) = o;
    }
}

// ---------------- K2: register-blocked GEMM Z = [h|agg] @ [Wf|Wp] + b ----------
// grid 256 (64-row tiles); block 256. thread: 8 row-pairs x 4 cols (f32x2).
// smem: Xs 16KB (pair-packed) + Ws 64KB (reused as Zs) = 80KB
__global__ void __launch_bounds__(256, 2) k_gemm(
        const float* __restrict__ h,
        const float* __restrict__ Wf, const float* __restrict__ bf,
        const float* __restrict__ Wp, const float* __restrict__ bp) {
    extern __shared__ float sm[];
    float* Xs = sm;            // 32 pairs * 64 k * 2 = 4096 floats
    float* Ws = sm + 4096;     // 64 k * 256 cols = 16384 floats
    int row0 = blockIdx.x * 64;
    int t = threadIdx.x;
    int rg = t >> 6;           // 0..3 : rows rg*16 .. rg*16+15
    int c4 = (t & 63) * 4;     // cols c4..c4+3

    unsigned long long acc[8][4];
    #pragma unroll
    for (int p = 0; p < 8; p++)
        #pragma unroll
        for (int c = 0; c < 4; c++) acc[p][c] = 0ull;

    for (int kt = 0; kt < 8; kt++) {
        // W tile: rows kt*64..kt*64+63 of [Wf|Wp] concatenated columns
        for (int i4 = t; i4 < 64*64; i4 += 256) {
            int kk = i4 >> 6, cc = (i4 & 63) * 4;
            float4 v = (cc < 128)
                ? *(const float4*)(Wf + (size_t)(kt*64 + kk)*128 + cc)
                : *(const float4*)(Wp + (size_t)(kt*64 + kk)*128 + (cc - 128));
            *(float4*)(Ws + kk*256 + cc) = v;
        }
        // X tile: 64 rows x 64 k, packed as row-pairs
        const float* src = (kt < 4)
            ? (h     + (size_t)row0*DIN + kt*64)
            : (g_agg + (size_t)row0*DIN + (kt-4)*64);
        for (int i4 = t; i4 < 1024; i4 += 256) {
            int p = i4 >> 5, r2 = (i4 >> 4) & 1, k4 = i4 & 15;
            float4 v = *(const float4*)(src + (size_t)(p*2 + r2)*DIN + k4*4);
            int base = p*128 + k4*8 + r2;
            Xs[base+0] = v.x; Xs[base+2] = v.y; Xs[base+4] = v.z; Xs[base+6] = v.w;
        }
        __syncthreads();

        #pragma unroll 4
        for (int k2 = 0; k2 < 32; k2++) {
            int k = k2*2;
            float4 wA = *(const float4*)(Ws + k*256 + c4);
            float4 wB = *(const float4*)(Ws + (k+1)*256 + c4);
            unsigned long long WA0 = dup2(wA.x), WA1 = dup2(wA.y),
                               WA2 = dup2(wA.z), WA3 = dup2(wA.w);
            unsigned long long WB0 = dup2(wB.x), WB1 = dup2(wB.y),
                               WB2 = dup2(wB.z), WB3 = dup2(wB.w);
            #pragma unroll
            for (int p = 0; p < 8; p++) {
                ulonglong2 X = *(const ulonglong2*)(Xs + (rg*8 + p)*128 + k2*4);
                acc[p][0] = fma2(X.x, WA0, acc[p][0]);
                acc[p][1] = fma2(X.x, WA1, acc[p][1]);
                acc[p][2] = fma2(X.x, WA2, acc[p][2]);
                acc[p][3] = fma2(X.x, WA3, acc[p][3]);
                acc[p][0] = fma2(X.y, WB0, acc[p][0]);
                acc[p][1] = fma2(X.y, WB1, acc[p][1]);
                acc[p][2] = fma2(X.y, WB2, acc[p][2]);
                acc[p][3] = fma2(X.y, WB3, acc[p][3]);
            }
        }
        __syncthreads();
    }

    // bias + stash Z into Ws (reused as Zs[64][256])
    float4 bias4 = (c4 < 128) ? *(const float4*)(bf + c4)
                              : *(const float4*)(bp + c4 - 128);
    float bb[4] = {bias4.x, bias4.y, bias4.z, bias4.w};
    #pragma unroll
    for (int p = 0; p < 8; p++) {
        int r = rg*16 + 2*p;
        #pragma unroll
        for (int c = 0; c < 4; c++) {
            float lo, hi;
            unpack2(acc[p][c], lo, hi);
            Ws[(r    )*256 + c4 + c] = lo + bb[c];
            Ws[(r + 1)*256 + c4 + c] = hi + bb[c];
        }
    }
    __syncthreads();

    // epilogue: 8 warps, 8 rows each
    int w = t >> 5, l = t & 31;
    const float4* Zs4 = (const float4*)Ws;
    for (int rr = 0; rr < 8; rr++) {
        int r = w*8 + rr;
        float4 f = Zs4[r*64 + l];
        float4 p = Zs4[r*64 + 32 + l];

        float ssf = f.x*f.x + f.y*f.y + f.z*f.z + f.w*f.w;
        float ssp = p.x*p.x + p.y*p.y + p.z*p.z + p.w*p.w;
        #pragma unroll
        for (int o = 16; o > 0; o >>= 1) {
            ssf += __shfl_xor_sync(0xffffffffu, ssf, o);
            ssp += __shfl_xor_sync(0xffffffffu, ssp, o);
        }
        float invf = rsqrtf(fmaxf(ssf, 1e-24f));
        float invp = rsqrtf(fmaxf(ssp, 1e-24f));

        f.x = fmaxf(f.x*invf, 0.f); f.y = fmaxf(f.y*invf, 0.f);
        f.z = fmaxf(f.z*invf, 0.f); f.w = fmaxf(f.w*invf, 0.f);
        float q0 = fmaxf(p.x*invp, 0.f), q1 = fmaxf(p.y*invp, 0.f);
        float q2 = fmaxf(p.z*invp, 0.f), q3 = fmaxf(p.w*invp, 0.f);

        float m = fmaxf(fmaxf(q0, q1), fmaxf(q2, q3));
        #pragma unroll
        for (int o = 16; o > 0; o >>= 1) m = fmaxf(m, __shfl_xor_sync(0xffffffffu, m, o));
        float e0 = __expf(q0 - m), e1 = __expf(q1 - m);
        float e2 = __expf(q2 - m), e3 = __expf(q3 - m);
        float s = e0 + e1 + e2 + e3;
        #pragma unroll
        for (int o = 16; o > 0; o >>= 1) s += __shfl_xor_sync(0xffffffffu, s, o);
        float isum = 1.0f / s;

        size_t grow = (size_t)(row0 + r)*DOUT;
        *(float4*)(g_feat + grow + l*4) = f;
        float4 a = make_float4(e0*isum, e1*isum, e2*isum, e3*isum);
        *(float4*)(g_assign + grow + l*4) = a;
    }
}

// ---------------- K4: AS[dst,:] = sum of assign[src,:] over in-edges --------
// grid (NB, 2 dst-halves); block 512; smem 128KB (whole assign graph)
__global__ void __launch_bounds__(512) k_as() {
    extern __shared__ float ss[];
    int b = blockIdx.x, dh = blockIdx.y, t = threadIdx.x;
    const float4* Sg4 = (const float4*)(g_assign + (size_t)b*NPER*DOUT);
    for (int i4 = t; i4 < 256*32; i4 += 512) ((float4*)ss)[i4] = Sg4[i4];
    __syncthreads();
    const ulonglong2* ssv = (const ulonglong2*)ss;   // idx = node*32 + l
    int w = t >> 5, l = t & 31;
    for (int ii = 0; ii < 8; ii++) {
        int dst = dh*128 + w*8 + ii;
        int gi = b*NPER + dst;
        int nn = g_ecnt[gi]; if (nn > MAXE) nn = MAXE;
        const unsigned char* lst = &g_elist[(size_t)gi*MAXE];
        unsigned long long a0 = 0, a1 = 0, b0 = 0, b1 = 0;
        int j = 0;
        for (; j + 4 <= nn; j += 4) {
            uchar4 s4 = *(const uchar4*)(lst + j);
            ulonglong2 v0 = ssv[s4.x*32 + l];
            ulonglong2 v1 = ssv[s4.y*32 + l];
            ulonglong2 v2 = ssv[s4.z*32 + l];
            ulonglong2 v3 = ssv[s4.w*32 + l];
            a0 = add2(a0, v0.x); a1 = add2(a1, v0.y);
            b0 = add2(b0, v1.x); b1 = add2(b1, v1.y);
            a0 = add2(a0, v2.x); a1 = add2(a1, v2.y);
            b0 = add2(b0, v3.x); b1 = add2(b1, v3.y);
        }
        for (; j < nn; j++) {
            ulonglong2 v = ssv[lst[j]*32 + l];
            a0 = add2(a0, v.x); a1 = add2(a1, v.y);
        }
        a0 = add2(a0, b0); a1 = add2(a1, b1);
        float x0, x1, x2, x3;
        unpack2(a0, x0, x1); unpack2(a1, x2, x3);
        *(float4*)(g_AS + (size_t)gi*DOUT + l*4) = make_float4(x0, x1, x2, x3);
    }
}

// ---------------- K5: out = S^T @ X (which=0 h_pool, which=1 adj blocks) -----
// grid (NB, 2); block 512 = 2 teams x 256; teams split contraction dim.
// smem: team tiles 2 x (S 32KB + X 32KB) = 128KB; team1 area reused for combine
__global__ void __launch_bounds__(512) k_pool(float* __restrict__ out) {
    extern __shared__ float sm[];
    int b = blockIdx.x, which = blockIdx.y;
    int t = threadIdx.x;
    int team = t >> 8;          // 0 or 1
    int tt = t & 255;
    int tk = tt >> 4, td = tt & 15;

    float* Ssm = sm + team*16384;          // 64 x 128
    float* Xsm = sm + team*16384 + 8192;   // 64 x 128

    const float* Sg = g_assign + (size_t)b*NPER*DOUT;
    const float* Xg = (which ? g_AS : g_feat) + (size_t)b*NPER*DOUT;

    unsigned long long acc[8][4];
    #pragma unroll
    for (int i = 0; i < 8; i++)
        #pragma unroll
        for (int j = 0; j < 4; j++) acc[i][j] = 0ull;

    for (int ci = 0; ci < 2; ci++) {
        int c = team*128 + ci*64;
        const float4* Sg4 = (const float4*)(Sg + c*128);
        const float4* Xg4 = (const float4*)(Xg + c*128);
        for (int i4 = tt; i4 < 64*32; i4 += 256) {
            ((float4*)Ssm)[i4] = Sg4[i4];
            ((float4*)Xsm)[i4] = Xg4[i4];
        }
        __syncthreads();
        for (int n = 0; n < 64; n++) {
            float4 a0 = ((const float4*)(Ssm + n*128))[tk*2];
            float4 a1 = ((const float4*)(Ssm + n*128))[tk*2 + 1];
            ulonglong2 x0 = ((const ulonglong2*)(Xsm + n*128))[td*2];
            ulonglong2 x1 = ((const ulonglong2*)(Xsm + n*128))[td*2 + 1];
            unsigned long long A[8] = {
                dup2(a0.x), dup2(a0.y), dup2(a0.z), dup2(a0.w),
                dup2(a1.x), dup2(a1.y), dup2(a1.z), dup2(a1.w)
            };
            #pragma unroll
            for (int i = 0; i < 8; i++) {
                acc[i][0] = fma2(x0.x, A[i], acc[i][0]);
                acc[i][1] = fma2(x0.y, A[i], acc[i][1]);
                acc[i][2] = fma2(x1.x, A[i], acc[i][2]);
                acc[i][3] = fma2(x1.y, A[i], acc[i][3]);
            }
        }
        __syncthreads();
    }

    // combine: team1 stashes partials in its tile area, team0 adds + stores
    float* cb = sm + 16384;    // 16384 floats = 64KB
    if (team == 1) {
        #pragma unroll
        for (int i = 0; i < 8; i++) {
            float* row = cb + (tk*8 + i)*128 + td*8;
            #pragma unroll
            for (int j = 0; j < 4; j++) {
                float lo, hi;
                unpack2(acc[i][j], lo, hi);
                row[2*j] = lo; row[2*j + 1] = hi;
            }
        }
    }
    __syncthreads();
    if (team == 0) {
        #pragma unroll
        for (int i = 0; i < 8; i++) {
            const float* row = cb + (tk*8 + i)*128 + td*8;
            size_t grow = (size_t)b*128 + tk*8 + i;
            size_t base = which ? (grow*ADJ_N + (size_t)b*128 + td*8)
                                : ((size_t)ADJ_ELEMS + grow*DOUT + td*8);
            #pragma unroll
            for (int j = 0; j < 4; j++) {
                float lo, hi;
                unpack2(acc[i][j], lo, hi);
                out[base + 2*j]     = lo + row[2*j];
                out[base + 2*j + 1] = hi + row[2*j + 1];
            }
        }
    }
}

// ---------------- launch ----------------
extern "C" void kernel_launch(void* const* d_in, const int* in_sizes, int n_in,
                              void* d_out, int out_size) {
    const float* h    = (const float*)d_in[0];
    const int*   esrc = (const int*)d_in[1];
    const int*   edst = (const int*)d_in[2];
    const float* Wf   = (const float*)d_in[3];
    const float* bf   = (const float*)d_in[4];
    const float* Wp   = (const float*)d_in[5];
    const float* bp   = (const float*)d_in[6];
    float* out = (float*)d_out;

    static cudaStream_t s_side = nullptr;
    static cudaEvent_t  e_fork = nullptr, e_join = nullptr;
    static bool attr_done = false;
    if (!s_side) {
        cudaStreamCreateWithFlags(&s_side, cudaStreamNonBlocking);
        cudaEventCreateWithFlags(&e_fork, cudaEventDisableTiming);
        cudaEventCreateWithFlags(&e_join, cudaEventDisableTiming);
    }
    if (!attr_done) {
        cudaFuncSetAttribute(k_agg,  cudaFuncAttributeMaxDynamicSharedMemorySize, 131072);
        cudaFuncSetAttribute(k_gemm, cudaFuncAttributeMaxDynamicSharedMemorySize, 81920);
        cudaFuncSetAttribute(k_as,   cudaFuncAttributeMaxDynamicSharedMemorySize, 131072);
        cudaFuncSetAttribute(k_pool, cudaFuncAttributeMaxDynamicSharedMemorySize, 131072);
        attr_done = true;
    }

    // fork: zero the adjacency output on a side stream, overlapped with compute
    cudaEventRecord(e_fork, 0);
    cudaStreamWaitEvent(s_side, e_fork, 0);
    cudaMemsetAsync(d_out, 0, (size_t)ADJ_ELEMS * sizeof(float), s_side);
    cudaEventRecord(e_join, s_side);

    k_build<<<NB, 256>>>(esrc, edst);
    k_agg<<<dim3(NB, 2), 512, 131072>>>(h);
    k_gemm<<<256, 256, 81920>>>(h, Wf, bf, Wp, bp);
    k_as<<<dim3(NB, 2), 512, 131072>>>();

    // join: adj must be zeroed before k_pool writes diagonal blocks
    cudaStreamWaitEvent(0, e_join, 0);
    k_pool<<<dim3(NB, 2), 512, 131072>>>(out);
}

// round 4
// speedup vs baseline: 2.1459x; 1.3985x over previous
#include <cuda_runtime.h>
#include <math.h>

#define NB   64
#define NPER 256
#define DIN  256
#define DOUT 128
#define EPER 8192
#define MAXE 192
#define ADJ_N 8192
#define ADJ_ELEMS (67108864u)   // 8192*8192

// ---------------- scratch ----------------
__device__ float g_T[NB*NPER*512];              // h @ [Wf_top|Wf_bot|Wp_top|Wp_bot]
__device__ float g_feat[NB*NPER*DOUT];
__device__ float g_assign[NB*NPER*DOUT];
__device__ float g_AS[NB*NPER*DOUT];
__device__ unsigned char g_elist[NB*NPER*MAXE];
__device__ int   g_ecnt[NB*NPER];
__device__ float g_ideg[NB*NPER];

// ---------------- f32x2 helpers ----------------
__device__ __forceinline__ unsigned long long fma2(unsigned long long a,
                                                   unsigned long long b,
                                                   unsigned long long c) {
    unsigned long long d;
    asm("fma.rn.f32x2 %0, %1, %2, %3;" : "=l"(d) : "l"(a), "l"(b), "l"(c));
    return d;
}
__device__ __forceinline__ unsigned long long add2(unsigned long long a,
                                                   unsigned long long b) {
    unsigned long long d;
    asm("add.rn.f32x2 %0, %1, %2;" : "=l"(d) : "l"(a), "l"(b));
    return d;
}
__device__ __forceinline__ unsigned long long dup2(float w) {
    unsigned long long d;
    asm("mov.b64 %0, {%1, %1};" : "=l"(d) : "f"(w));
    return d;
}
__device__ __forceinline__ void unpack2(unsigned long long v, float& lo, float& hi) {
    asm("mov.b64 {%0, %1}, %2;" : "=f"(lo), "=f"(hi) : "l"(v));
}

// ---------------- K-build: per-dst edge lists + degrees ----------------
__global__ void k_build(const int* __restrict__ esrc, const int* __restrict__ edst) {
    int b = blockIdx.x;
    __shared__ int scnt[NPER];
    for (int i = threadIdx.x; i < NPER; i += blockDim.x) scnt[i] = 0;
    __syncthreads();
    const int* s = esrc + b*EPER;
    const int* d = edst + b*EPER;
    for (int e = threadIdx.x; e < EPER; e += blockDim.x) {
        int dst = d[e];
        int src = s[e];
        int pos = atomicAdd(&scnt[dst], 1);
        if (pos < MAXE) g_elist[(b*NPER + dst)*MAXE + pos] = (unsigned char)src;
    }
    __syncthreads();
    for (int i = threadIdx.x; i < NPER; i += blockDim.x) {
        int c = scnt[i];
        g_ecnt[b*NPER + i] = c;
        g_ideg[b*NPER + i] = 1.0f / (float)(c > 0 ? c : 1);
    }
}

// ---------------- K-gemm: T = h @ Wcat ;  Wcat[256,512] ----------------
__global__ void __launch_bounds__(256, 2) k_gemm(
        const float* __restrict__ h,
        const float* __restrict__ Wf, const float* __restrict__ Wp) {
    extern __shared__ float sm[];
    float* Xs = sm;            // 4096 floats (16KB)
    float* Ws = sm + 4096;     // 16384 floats (64KB)
    int row0 = blockIdx.x * 64;
    int ct   = blockIdx.y;
    int t = threadIdx.x;
    int rg = t >> 6;
    int c4 = (t & 63) * 4;

    unsigned long long acc[8][4];
    #pragma unroll
    for (int p = 0; p < 8; p++)
        #pragma unroll
        for (int c = 0; c < 4; c++) acc[p][c] = 0ull;

    for (int kt = 0; kt < 4; kt++) {
        for (int i4 = t; i4 < 64*64; i4 += 256) {
            int kk = i4 >> 6, cc = (i4 & 63) * 4;
            int j = ct*256 + cc;
            int seg = j >> 7;
            const float* Wb = (seg < 2) ? Wf : Wp;
            int krow = kt*64 + kk + ((seg & 1) ? 256 : 0);
            float4 v = *(const float4*)(Wb + (size_t)krow*128 + (j & 127));
            *(float4*)(Ws + kk*256 + cc) = v;
        }
        const float* src = h + (size_t)row0*DIN + kt*64;
        for (int i4 = t; i4 < 1024; i4 += 256) {
            int p = i4 >> 5, r2 = (i4 >> 4) & 1, k4 = i4 & 15;
            float4 v = *(const float4*)(src + (size_t)(p*2 + r2)*DIN + k4*4);
            int base = p*128 + k4*8 + r2;
            Xs[base+0] = v.x; Xs[base+2] = v.y; Xs[base+4] = v.z; Xs[base+6] = v.w;
        }
        __syncthreads();

        #pragma unroll 4
        for (int k2 = 0; k2 < 32; k2++) {
            int k = k2*2;
            float4 wA = *(const float4*)(Ws + k*256 + c4);
            float4 wB = *(const float4*)(Ws + (k+1)*256 + c4);
            unsigned long long WA0 = dup2(wA.x), WA1 = dup2(wA.y),
                               WA2 = dup2(wA.z), WA3 = dup2(wA.w);
            unsigned long long WB0 = dup2(wB.x), WB1 = dup2(wB.y),
                               WB2 = dup2(wB.z), WB3 = dup2(wB.w);
            #pragma unroll
            for (int p = 0; p < 8; p++) {
                ulonglong2 X = *(const ulonglong2*)(Xs + (rg*8 + p)*128 + k2*4);
                acc[p][0] = fma2(X.x, WA0, acc[p][0]);
                acc[p][1] = fma2(X.x, WA1, acc[p][1]);
                acc[p][2] = fma2(X.x, WA2, acc[p][2]);
                acc[p][3] = fma2(X.x, WA3, acc[p][3]);
                acc[p][0] = fma2(X.y, WB0, acc[p][0]);
                acc[p][1] = fma2(X.y, WB1, acc[p][1]);
                acc[p][2] = fma2(X.y, WB2, acc[p][2]);
                acc[p][3] = fma2(X.y, WB3, acc[p][3]);
            }
        }
        __syncthreads();
    }

    #pragma unroll
    for (int p = 0; p < 8; p++) {
        int r = row0 + rg*16 + 2*p;
        float lo0, hi0, lo1, hi1, lo2, hi2, lo3, hi3;
        unpack2(acc[p][0], lo0, hi0);
        unpack2(acc[p][1], lo1, hi1);
        unpack2(acc[p][2], lo2, hi2);
        unpack2(acc[p][3], lo3, hi3);
        *(float4*)(g_T + (size_t)r*512 + ct*256 + c4)     = make_float4(lo0, lo1, lo2, lo3);
        *(float4*)(g_T + (size_t)(r+1)*512 + ct*256 + c4) = make_float4(hi0, hi1, hi2, hi3);
    }
}

// ---------------- K-fuse: Z = T_top + ideg*gather(T_bot) + bias, epilogue ------
// grid (NB, 2: which 0=feat 1=pool); block 1024; smem 128KB
__global__ void __launch_bounds__(1024) k_fuse(const float* __restrict__ bf,
                                               const float* __restrict__ bp) {
    extern __shared__ float ts[];
    int b = blockIdx.x, which = blockIdx.y, t = threadIdx.x;
    int top_off = which*256, bot_off = which*256 + 128;
    for (int i4 = t; i4 < 256*32; i4 += 1024) {
        int node = i4 >> 5, f4 = i4 & 31;
        ((float4*)ts)[i4] = *(const float4*)(g_T + (size_t)(b*NPER + node)*512 + bot_off + f4*4);
    }
    __syncthreads();
    const ulonglong2* tsv = (const ulonglong2*)ts;
    int w = t >> 5, l = t & 31;
    const float* bias = which ? bp : bf;
    float4 bias4 = *(const float4*)(bias + l*4);

    for (int ii = 0; ii < 8; ii++) {
        int dst = w*8 + ii;
        int gi = b*NPER + dst;
        int nn = g_ecnt[gi]; if (nn > MAXE) nn = MAXE;
        float ideg = g_ideg[gi];
        const unsigned char* lst = &g_elist[(size_t)gi*MAXE];
        unsigned long long a0 = 0, a1 = 0, b0 = 0, b1 = 0;
        int j = 0;
        for (; j + 4 <= nn; j += 4) {
            uchar4 s4 = *(const uchar4*)(lst + j);
            ulonglong2 v0 = tsv[s4.x*32 + l];
            ulonglong2 v1 = tsv[s4.y*32 + l];
            ulonglong2 v2 = tsv[s4.z*32 + l];
            ulonglong2 v3 = tsv[s4.w*32 + l];
            a0 = add2(a0, v0.x); a1 = add2(a1, v0.y);
            b0 = add2(b0, v1.x); b1 = add2(b1, v1.y);
            a0 = add2(a0, v2.x); a1 = add2(a1, v2.y);
            b0 = add2(b0, v3.x); b1 = add2(b1, v3.y);
        }
        for (; j < nn; j++) {
            ulonglong2 v = tsv[lst[j]*32 + l];
            a0 = add2(a0, v.x); a1 = add2(a1, v.y);
        }
        a0 = add2(a0, b0); a1 = add2(a1, b1);
        float s0, s1, s2, s3;
        unpack2(a0, s0, s1); unpack2(a1, s2, s3);

        float4 top = *(const float4*)(g_T + (size_t)gi*512 + top_off + l*4);
        float z0 = fmaf(ideg, s0, top.x) + bias4.x;
        float z1 = fmaf(ideg, s1, top.y) + bias4.y;
        float z2 = fmaf(ideg, s2, top.z) + bias4.z;
        float z3 = fmaf(ideg, s3, top.w) + bias4.w;

        float ss = z0*z0 + z1*z1 + z2*z2 + z3*z3;
        #pragma unroll
        for (int o = 16; o > 0; o >>= 1) ss += __shfl_xor_sync(0xffffffffu, ss, o);
        float inv = rsqrtf(fmaxf(ss, 1e-24f));
        z0 = fmaxf(z0*inv, 0.f); z1 = fmaxf(z1*inv, 0.f);
        z2 = fmaxf(z2*inv, 0.f); z3 = fmaxf(z3*inv, 0.f);

        if (which == 0) {
            *(float4*)(g_feat + (size_t)gi*DOUT + l*4) = make_float4(z0, z1, z2, z3);
        } else {
            float m = fmaxf(fmaxf(z0, z1), fmaxf(z2, z3));
            #pragma unroll
            for (int o = 16; o > 0; o >>= 1) m = fmaxf(m, __shfl_xor_sync(0xffffffffu, m, o));
            float e0 = __expf(z0 - m), e1 = __expf(z1 - m);
            float e2 = __expf(z2 - m), e3 = __expf(z3 - m);
            float s = e0 + e1 + e2 + e3;
            #pragma unroll
            for (int o = 16; o > 0; o >>= 1) s += __shfl_xor_sync(0xffffffffu, s, o);
            float isum = 1.0f / s;
            *(float4*)(g_assign + (size_t)gi*DOUT + l*4) =
                make_float4(e0*isum, e1*isum, e2*isum, e3*isum);
        }
    }
}

// ---------------- K-as: AS[dst,:] = sum of assign[src,:] over in-edges --------
__global__ void __launch_bounds__(1024) k_as() {
    extern __shared__ float ss[];
    int b = blockIdx.x, dh = blockIdx.y, t = threadIdx.x;
    const float4* Sg4 = (const float4*)(g_assign + (size_t)b*NPER*DOUT);
    for (int i4 = t; i4 < 256*32; i4 += 1024) ((float4*)ss)[i4] = Sg4[i4];
    __syncthreads();
    const ulonglong2* ssv = (const ulonglong2*)ss;
    int w = t >> 5, l = t & 31;
    for (int ii = 0; ii < 4; ii++) {
        int dst = dh*128 + w*4 + ii;
        int gi = b*NPER + dst;
        int nn = g_ecnt[gi]; if (nn > MAXE) nn = MAXE;
        const unsigned char* lst = &g_elist[(size_t)gi*MAXE];
        unsigned long long a0 = 0, a1 = 0, b0 = 0, b1 = 0;
        int j = 0;
        for (; j + 4 <= nn; j += 4) {
            uchar4 s4 = *(const uchar4*)(lst + j);
            ulonglong2 v0 = ssv[s4.x*32 + l];
            ulonglong2 v1 = ssv[s4.y*32 + l];
            ulonglong2 v2 = ssv[s4.z*32 + l];
            ulonglong2 v3 = ssv[s4.w*32 + l];
            a0 = add2(a0, v0.x); a1 = add2(a1, v0.y);
            b0 = add2(b0, v1.x); b1 = add2(b1, v1.y);
            a0 = add2(a0, v2.x); a1 = add2(a1, v2.y);
            b0 = add2(b0, v3.x); b1 = add2(b1, v3.y);
        }
        for (; j < nn; j++) {
            ulonglong2 v = ssv[lst[j]*32 + l];
            a0 = add2(a0, v.x); a1 = add2(a1, v.y);
        }
        a0 = add2(a0, b0); a1 = add2(a1, b1);
        float x0, x1, x2, x3;
        unpack2(a0, x0, x1); unpack2(a1, x2, x3);
        *(float4*)(g_AS + (size_t)gi*DOUT + l*4) = make_float4(x0, x1, x2, x3);
    }
}

// ---------------- K-pool: out = S^T @ X (which=0 h_pool, which=1 adj blocks) ---
__global__ void __launch_bounds__(512) k_pool(float* __restrict__ out) {
    extern __shared__ float sm[];
    int b = blockIdx.x, which = blockIdx.y;
    int t = threadIdx.x;
    int team = t >> 8;
    int tt = t & 255;
    int tk = tt >> 4, td = tt & 15;

    float* Ssm = sm + team*16384;
    float* Xsm = sm + team*16384 + 8192;

    const float* Sg = g_assign + (size_t)b*NPER*DOUT;
    const float* Xg = (which ? g_AS : g_feat) + (size_t)b*NPER*DOUT;

    unsigned long long acc[8][4];
    #pragma unroll
    for (int i = 0; i < 8; i++)
        #pragma unroll
        for (int j = 0; j < 4; j++) acc[i][j] = 0ull;

    for (int ci = 0; ci < 2; ci++) {
        int c = team*128 + ci*64;
        const float4* Sg4 = (const float4*)(Sg + c*128);
        const float4* Xg4 = (const float4*)(Xg + c*128);
        for (int i4 = tt; i4 < 64*32; i4 += 256) {
            ((float4*)Ssm)[i4] = Sg4[i4];
            ((float4*)Xsm)[i4] = Xg4[i4];
        }
        __syncthreads();
        for (int n = 0; n < 64; n++) {
            float4 a0 = ((const float4*)(Ssm + n*128))[tk*2];
            float4 a1 = ((const float4*)(Ssm + n*128))[tk*2 + 1];
            ulonglong2 x0 = ((const ulonglong2*)(Xsm + n*128))[td*2];
            ulonglong2 x1 = ((const ulonglong2*)(Xsm + n*128))[td*2 + 1];
            unsigned long long A[8] = {
                dup2(a0.x), dup2(a0.y), dup2(a0.z), dup2(a0.w),
                dup2(a1.x), dup2(a1.y), dup2(a1.z), dup2(a1.w)
            };
            #pragma unroll
            for (int i = 0; i < 8; i++) {
                acc[i][0] = fma2(x0.x, A[i], acc[i][0]);
                acc[i][1] = fma2(x0.y, A[i], acc[i][1]);
                acc[i][2] = fma2(x1.x, A[i], acc[i][2]);
                acc[i][3] = fma2(x1.y, A[i], acc[i][3]);
            }
        }
        __syncthreads();
    }

    float* cb = sm + 16384;
    if (team == 1) {
        #pragma unroll
        for (int i = 0; i < 8; i++) {
            float* row = cb + (tk*8 + i)*128 + td*8;
            #pragma unroll
            for (int j = 0; j < 4; j++) {
                float lo, hi;
                unpack2(acc[i][j], lo, hi);
                row[2*j] = lo; row[2*j + 1] = hi;
            }
        }
    }
    __syncthreads();
    if (team == 0) {
        #pragma unroll
        for (int i = 0; i < 8; i++) {
            const float* row = cb + (tk*8 + i)*128 + td*8;
            size_t grow = (size_t)b*128 + tk*8 + i;
            size_t base = which ? (grow*ADJ_N + (size_t)b*128 + td*8)
                                : ((size_t)ADJ_ELEMS + grow*DOUT + td*8);
            #pragma unroll
            for (int j = 0; j < 4; j++) {
                float lo, hi;
                unpack2(acc[i][j], lo, hi);
                out[base + 2*j]     = lo + row[2*j];
                out[base + 2*j + 1] = hi + row[2*j + 1];
            }
        }
    }
}

// ---------------- launch ----------------
extern "C" void kernel_launch(void* const* d_in, const int* in_sizes, int n_in,
                              void* d_out, int out_size) {
    const float* h    = (const float*)d_in[0];
    const int*   esrc = (const int*)d_in[1];
    const int*   edst = (const int*)d_in[2];
    const float* Wf   = (const float*)d_in[3];
    const float* bf   = (const float*)d_in[4];
    const float* Wp   = (const float*)d_in[5];
    const float* bp   = (const float*)d_in[6];
    float* out = (float*)d_out;

    static cudaStream_t s_side = nullptr;
    static cudaEvent_t  e_fork = nullptr, e_build = nullptr, e_join = nullptr;
    static bool attr_done = false;
    if (!s_side) {
        cudaStreamCreateWithFlags(&s_side, cudaStreamNonBlocking);
        cudaEventCreateWithFlags(&e_fork,  cudaEventDisableTiming);
        cudaEventCreateWithFlags(&e_build, cudaEventDisableTiming);
        cudaEventCreateWithFlags(&e_join,  cudaEventDisableTiming);
    }
    if (!attr_done) {
        cudaFuncSetAttribute(k_gemm, cudaFuncAttributeMaxDynamicSharedMemorySize, 81920);
        cudaFuncSetAttribute(k_fuse, cudaFuncAttributeMaxDynamicSharedMemorySize, 131072);
        cudaFuncSetAttribute(k_as,   cudaFuncAttributeMaxDynamicSharedMemorySize, 131072);
        cudaFuncSetAttribute(k_pool, cudaFuncAttributeMaxDynamicSharedMemorySize, 131072);
        attr_done = true;
    }

    // side stream: edge-list build, then adj memset (overlap with GEMM)
    cudaEventRecord(e_fork, 0);
    cudaStreamWaitEvent(s_side, e_fork, 0);
    k_build<<<NB, 256, 0, s_side>>>(esrc, edst);
    cudaEventRecord(e_build, s_side);
    cudaMemsetAsync(d_out, 0, (size_t)ADJ_ELEMS * sizeof(float), s_side);
    cudaEventRecord(e_join, s_side);

    // main stream
    k_gemm<<<dim3(256, 2), 256, 81920>>>(h, Wf, Wp);
    cudaStreamWaitEvent(0, e_build, 0);
    k_fuse<<<dim3(NB, 2), 1024, 131072>>>(bf, bp);
    k_as<<<dim3(NB, 2), 1024, 131072>>>();
    cudaStreamWaitEvent(0, e_join, 0);
    k_pool<<<dim3(NB, 2), 512, 131072>>>(out);
}

// round 7
// speedup vs baseline: 2.7898x; 1.3001x over previous
#include <cuda_runtime.h>
#include <cuda_bf16.h>
#include <math.h>
#include <stdint.h>

#define NB   64
#define NPER 256
#define DIN  256
#define DOUT 128
#define EPER 8192
#define MAXE 192
#define ADJ_N 8192
#define ADJ_ELEMS (67108864u)
#define NROWS (NB*NPER)          // 16384

// ---------------- scratch ----------------
__device__ float g_T[NROWS*512];                // X @ Wcat  (cols: Wf_top|Wf_bot|Wp_top|Wp_bot)
__device__ float g_feat[NROWS*DOUT];
__device__ float g_assign[NROWS*DOUT];
__device__ float g_AS[NROWS*DOUT];
__device__ unsigned char g_elist[NROWS*MAXE];
__device__ int   g_ecnt[NROWS];
__device__ float g_ideg[NROWS];
// fragment-major bf16x2 words:
//   X:  [m_tile(1024)][k_chunk(16)][lane(32)][reg(4)]
//   WT: [n_tile(64)]  [k_chunk(16)][lane(32)][reg(2)]
__device__ unsigned int g_Xh[NROWS*128];
__device__ unsigned int g_Xl[NROWS*128];
__device__ unsigned int g_WTh[512*128];
__device__ unsigned int g_WTl[512*128];

// ---------------- f32x2 helpers ----------------
__device__ __forceinline__ unsigned long long fma2(unsigned long long a,
                                                   unsigned long long b,
                                                   unsigned long long c) {
    unsigned long long d;
    asm("fma.rn.f32x2 %0, %1, %2, %3;" : "=l"(d) : "l"(a), "l"(b), "l"(c));
    return d;
}
__device__ __forceinline__ unsigned long long add2(unsigned long long a,
                                                   unsigned long long b) {
    unsigned long long d;
    asm("add.rn.f32x2 %0, %1, %2;" : "=l"(d) : "l"(a), "l"(b));
    return d;
}
__device__ __forceinline__ unsigned long long dup2(float w) {
    unsigned long long d;
    asm("mov.b64 %0, {%1, %1};" : "=l"(d) : "f"(w));
    return d;
}
__device__ __forceinline__ void unpack2(unsigned long long v, float& lo, float& hi) {
    asm("mov.b64 {%0, %1}, %2;" : "=f"(lo), "=f"(hi) : "l"(v));
}

// ---------------- mma.sync bf16 (baseline PTX, no 'a' feature needed) ----------
__device__ __forceinline__ void mma16816(float* c, const uint32_t* a, const uint32_t* b) {
    asm volatile(
        "mma.sync.aligned.m16n8k16.row.col.f32.bf16.bf16.f32 "
        "{%0,%1,%2,%3}, {%4,%5,%6,%7}, {%8,%9}, {%0,%1,%2,%3};"
        : "+f"(c[0]), "+f"(c[1]), "+f"(c[2]), "+f"(c[3])
        : "r"(a[0]), "r"(a[1]), "r"(a[2]), "r"(a[3]), "r"(b[0]), "r"(b[1]));
}

// ---------------- K-build ----------------
__global__ void k_build(const int* __restrict__ esrc, const int* __restrict__ edst) {
    int b = blockIdx.x;
    __shared__ int scnt[NPER];
    for (int i = threadIdx.x; i < NPER; i += blockDim.x) scnt[i] = 0;
    __syncthreads();
    const int* s = esrc + b*EPER;
    const int* d = edst + b*EPER;
    for (int e = threadIdx.x; e < EPER; e += blockDim.x) {
        int dst = d[e];
        int src = s[e];
        int pos = atomicAdd(&scnt[dst], 1);
        if (pos < MAXE) g_elist[(b*NPER + dst)*MAXE + pos] = (unsigned char)src;
    }
    __syncthreads();
    for (int i = threadIdx.x; i < NPER; i += blockDim.x) {
        int c = scnt[i];
        g_ecnt[b*NPER + i] = c;
        g_ideg[b*NPER + i] = 1.0f / (float)(c > 0 ? c : 1);
    }
}

// ---------------- K-prep: bf16 hi/lo split into mma-fragment layout ------------
__device__ __forceinline__ void split2(float a, float b, unsigned int& hi, unsigned int& lo) {
    __nv_bfloat16 ah = __float2bfloat16(a);
    __nv_bfloat16 bh = __float2bfloat16(b);
    __nv_bfloat16 al = __float2bfloat16(a - __bfloat162float(ah));
    __nv_bfloat16 bl = __float2bfloat16(b - __bfloat162float(bh));
    __nv_bfloat162 hh; hh.x = ah; hh.y = bh;
    __nv_bfloat162 ll; ll.x = al; ll.y = bl;
    hi = *reinterpret_cast<unsigned int*>(&hh);
    lo = *reinterpret_cast<unsigned int*>(&ll);
}

__global__ void k_prep(const float* __restrict__ h,
                       const float* __restrict__ Wf, const float* __restrict__ Wp) {
    int idx = blockIdx.x*256 + threadIdx.x;
    if (blockIdx.x < 8192) {
        // X fragments: idx = mt*2048 + kc*128 + lane*4 + reg  (2,097,152 words)
        int reg = idx & 3, lane = (idx >> 2) & 31, kc = (idx >> 7) & 15, mt = idx >> 11;
        int g = lane >> 2, tg = lane & 3;
        int row = mt*16 + g + (reg & 1)*8;
        int w = tg + (reg >> 1)*4;
        const float* hp = h + (size_t)row*DIN + (kc*8 + w)*2;
        unsigned int hi, lo;
        split2(hp[0], hp[1], hi, lo);
        g_Xh[idx] = hi;
        g_Xl[idx] = lo;
    } else {
        int widx = idx - 8192*256;       // [0, 65536)
        int reg = widx & 1, lane = (widx >> 1) & 31, kc = (widx >> 6) & 15, nt = widx >> 10;
        int g = lane >> 2, tg = lane & 3;
        int n = nt*8 + g;
        int w = tg + reg*4;
        int k = (kc*8 + w)*2;
        int seg = n >> 7;
        const float* Wb = (seg < 2) ? Wf : Wp;
        int col = n & 127;
        int krow = k + ((seg & 1) ? 256 : 0);
        float x0 = Wb[(size_t)krow*128 + col];
        float x1 = Wb[(size_t)(krow+1)*128 + col];
        unsigned int hi, lo;
        split2(x0, x1, hi, lo);
        g_WTh[widx] = hi;
        g_WTl[widx] = lo;
    }
}

// ---------------- K-gemm (HMMA): T = X @ Wcat via 3-pass bf16 split ------------
// grid (128, 4); block 256 = 8 warps (2 m-groups x 4 n-groups).
// warp tile: 64 rows x 32 cols = 4x4 m16n8 tiles; K=256 in 16 chunks of 16.
__global__ void __launch_bounds__(256) k_gemm_mma() {
    int t = threadIdx.x, lane = t & 31, w = t >> 5;
    int wm = w & 1, wn = w >> 1;
    int mt0 = blockIdx.x*8 + wm*4;      // m-tile (16 rows each)
    int nt0 = blockIdx.y*16 + wn*4;     // n-tile (8 cols each)

    float acc[4][4][4];
    #pragma unroll
    for (int i = 0; i < 4; i++)
        #pragma unroll
        for (int j = 0; j < 4; j++)
            #pragma unroll
            for (int r = 0; r < 4; r++) acc[i][j][r] = 0.f;

    const uint4* Xh4 = (const uint4*)g_Xh;
    const uint4* Xl4 = (const uint4*)g_Xl;
    const uint2* Wh2 = (const uint2*)g_WTh;
    const uint2* Wl2 = (const uint2*)g_WTl;

    for (int kc = 0; kc < 16; kc++) {
        uint4 Ah[4], Al[4];
        uint2 Bh[4], Bl[4];
        #pragma unroll
        for (int i = 0; i < 4; i++) {
            int off = ((mt0 + i)*16 + kc)*32 + lane;
            Ah[i] = Xh4[off];
            Al[i] = Xl4[off];
        }
        #pragma unroll
        for (int j = 0; j < 4; j++) {
            int off = ((nt0 + j)*16 + kc)*32 + lane;
            Bh[j] = Wh2[off];
            Bl[j] = Wl2[off];
        }
        #pragma unroll
        for (int i = 0; i < 4; i++) {
            #pragma unroll
            for (int j = 0; j < 4; j++) {
                mma16816(acc[i][j], (const uint32_t*)&Ah[i], (const uint32_t*)&Bh[j]);
                mma16816(acc[i][j], (const uint32_t*)&Ah[i], (const uint32_t*)&Bl[j]);
                mma16816(acc[i][j], (const uint32_t*)&Al[i], (const uint32_t*)&Bh[j]);
            }
        }
    }

    int g = lane >> 2, tg = lane & 3;
    #pragma unroll
    for (int i = 0; i < 4; i++) {
        #pragma unroll
        for (int j = 0; j < 4; j++) {
            size_t row = (size_t)(mt0 + i)*16 + g;
            size_t col = (size_t)(nt0 + j)*8 + tg*2;
            *(float2*)(g_T + row*512 + col)       = make_float2(acc[i][j][0], acc[i][j][1]);
            *(float2*)(g_T + (row + 8)*512 + col) = make_float2(acc[i][j][2], acc[i][j][3]);
        }
    }
}

// ---------------- K-fuse: Z = T_top + ideg*gather(T_bot) + bias, epilogue ------
__global__ void __launch_bounds__(1024) k_fuse(const float* __restrict__ bf,
                                               const float* __restrict__ bp) {
    extern __shared__ float ts[];
    int b = blockIdx.x, which = blockIdx.y, t = threadIdx.x;
    int top_off = which*256, bot_off = which*256 + 128;
    for (int i4 = t; i4 < 256*32; i4 += 1024) {
        int node = i4 >> 5, f4 = i4 & 31;
        ((float4*)ts)[i4] = *(const float4*)(g_T + (size_t)(b*NPER + node)*512 + bot_off + f4*4);
    }
    __syncthreads();
    const ulonglong2* tsv = (const ulonglong2*)ts;
    int w = t >> 5, l = t & 31;
    const float* bias = which ? bp : bf;
    float4 bias4 = *(const float4*)(bias + l*4);

    for (int ii = 0; ii < 8; ii++) {
        int dst = w*8 + ii;
        int gi = b*NPER + dst;
        int nn = g_ecnt[gi]; if (nn > MAXE) nn = MAXE;
        float ideg = g_ideg[gi];
        const unsigned char* lst = &g_elist[(size_t)gi*MAXE];
        unsigned long long a0 = 0, a1 = 0, b0 = 0, b1 = 0;
        int j = 0;
        for (; j + 4 <= nn; j += 4) {
            uchar4 s4 = *(const uchar4*)(lst + j);
            ulonglong2 v0 = tsv[s4.x*32 + l];
            ulonglong2 v1 = tsv[s4.y*32 + l];
            ulonglong2 v2 = tsv[s4.z*32 + l];
            ulonglong2 v3 = tsv[s4.w*32 + l];
            a0 = add2(a0, v0.x); a1 = add2(a1, v0.y);
            b0 = add2(b0, v1.x); b1 = add2(b1, v1.y);
            a0 = add2(a0, v2.x); a1 = add2(a1, v2.y);
            b0 = add2(b0, v3.x); b1 = add2(b1, v3.y);
        }
        for (; j < nn; j++) {
            ulonglong2 v = tsv[lst[j]*32 + l];
            a0 = add2(a0, v.x); a1 = add2(a1, v.y);
        }
        a0 = add2(a0, b0); a1 = add2(a1, b1);
        float s0, s1, s2, s3;
        unpack2(a0, s0, s1); unpack2(a1, s2, s3);

        float4 top = *(const float4*)(g_T + (size_t)gi*512 + top_off + l*4);
        float z0 = fmaf(ideg, s0, top.x) + bias4.x;
        float z1 = fmaf(ideg, s1, top.y) + bias4.y;
        float z2 = fmaf(ideg, s2, top.z) + bias4.z;
        float z3 = fmaf(ideg, s3, top.w) + bias4.w;

        float ss = z0*z0 + z1*z1 + z2*z2 + z3*z3;
        #pragma unroll
        for (int o = 16; o > 0; o >>= 1) ss += __shfl_xor_sync(0xffffffffu, ss, o);
        float inv = rsqrtf(fmaxf(ss, 1e-24f));
        z0 = fmaxf(z0*inv, 0.f); z1 = fmaxf(z1*inv, 0.f);
        z2 = fmaxf(z2*inv, 0.f); z3 = fmaxf(z3*inv, 0.f);

        if (which == 0) {
            *(float4*)(g_feat + (size_t)gi*DOUT + l*4) = make_float4(z0, z1, z2, z3);
        } else {
            float m = fmaxf(fmaxf(z0, z1), fmaxf(z2, z3));
            #pragma unroll
            for (int o = 16; o > 0; o >>= 1) m = fmaxf(m, __shfl_xor_sync(0xffffffffu, m, o));
            float e0 = __expf(z0 - m), e1 = __expf(z1 - m);
            float e2 = __expf(z2 - m), e3 = __expf(z3 - m);
            float s = e0 + e1 + e2 + e3;
            #pragma unroll
            for (int o = 16; o > 0; o >>= 1) s += __shfl_xor_sync(0xffffffffu, s, o);
            float isum = 1.0f / s;
            *(float4*)(g_assign + (size_t)gi*DOUT + l*4) =
                make_float4(e0*isum, e1*isum, e2*isum, e3*isum);
        }
    }
}

// ---------------- K-as: AS = A @ assign ; feature/dst split ----------------
// grid (NB, 2 fh, 2 dh); block 1024; smem 64KB (256 nodes x 64 feats)
__global__ void __launch_bounds__(1024) k_as() {
    extern __shared__ float ss[];
    int b = blockIdx.x, fh = blockIdx.y, dh = blockIdx.z, t = threadIdx.x;
    for (int i4 = t; i4 < 256*16; i4 += 1024) {
        int node = i4 >> 4, f4 = i4 & 15;
        ((float4*)ss)[i4] = *(const float4*)(g_assign + (size_t)(b*NPER + node)*DOUT + fh*64 + f4*4);
    }
    __syncthreads();
    const unsigned long long* ssv = (const unsigned long long*)ss;  // node*32 + l
    int w = t >> 5, l = t & 31;
    for (int ii = 0; ii < 4; ii++) {
        int dst = dh*128 + w*4 + ii;
        int gi = b*NPER + dst;
        int nn = g_ecnt[gi]; if (nn > MAXE) nn = MAXE;
        const unsigned char* lst = &g_elist[(size_t)gi*MAXE];
        unsigned long long a0 = 0, a1 = 0, a2 = 0, a3 = 0;
        int j = 0;
        for (; j + 4 <= nn; j += 4) {
            uchar4 s4 = *(const uchar4*)(lst + j);
            a0 = add2(a0, ssv[s4.x*32 + l]);
            a1 = add2(a1, ssv[s4.y*32 + l]);
            a2 = add2(a2, ssv[s4.z*32 + l]);
            a3 = add2(a3, ssv[s4.w*32 + l]);
        }
        for (; j < nn; j++) a0 = add2(a0, ssv[lst[j]*32 + l]);
        a0 = add2(add2(a0, a1), add2(a2, a3));
        float lo, hi;
        unpack2(a0, lo, hi);
        *(float2*)(g_AS + (size_t)gi*DOUT + fh*64 + l*2) = make_float2(lo, hi);
    }
}

// ---------------- K-pool: out = S^T @ X ----------------
__global__ void __launch_bounds__(512) k_pool(float* __restrict__ out) {
    extern __shared__ float sm[];
    int b = blockIdx.x, which = blockIdx.y;
    int t = threadIdx.x;
    int team = t >> 8;
    int tt = t & 255;
    int tk = tt >> 4, td = tt & 15;

    float* Ssm = sm + team*16384;
    float* Xsm = sm + team*16384 + 8192;

    const float* Sg = g_assign + (size_t)b*NPER*DOUT;
    const float* Xg = (which ? g_AS : g_feat) + (size_t)b*NPER*DOUT;

    unsigned long long acc[8][4];
    #pragma unroll
    for (int i = 0; i < 8; i++)
        #pragma unroll
        for (int j = 0; j < 4; j++) acc[i][j] = 0ull;

    for (int ci = 0; ci < 2; ci++) {
        int c = team*128 + ci*64;
        const float4* Sg4 = (const float4*)(Sg + c*128);
        const float4* Xg4 = (const float4*)(Xg + c*128);
        for (int i4 = tt; i4 < 64*32; i4 += 256) {
            ((float4*)Ssm)[i4] = Sg4[i4];
            ((float4*)Xsm)[i4] = Xg4[i4];
        }
        __syncthreads();
        for (int n = 0; n < 64; n++) {
            float4 a0 = ((const float4*)(Ssm + n*128))[tk*2];
            float4 a1 = ((const float4*)(Ssm + n*128))[tk*2 + 1];
            ulonglong2 x0 = ((const ulonglong2*)(Xsm + n*128))[td*2];
            ulonglong2 x1 = ((const ulonglong2*)(Xsm + n*128))[td*2 + 1];
            unsigned long long A[8] = {
                dup2(a0.x), dup2(a0.y), dup2(a0.z), dup2(a0.w),
                dup2(a1.x), dup2(a1.y), dup2(a1.z), dup2(a1.w)
            };
            #pragma unroll
            for (int i = 0; i < 8; i++) {
                acc[i][0] = fma2(x0.x, A[i], acc[i][0]);
                acc[i][1] = fma2(x0.y, A[i], acc[i][1]);
                acc[i][2] = fma2(x1.x, A[i], acc[i][2]);
                acc[i][3] = fma2(x1.y, A[i], acc[i][3]);
            }
        }
        __syncthreads();
    }

    float* cb = sm + 16384;
    if (team == 1) {
        #pragma unroll
        for (int i = 0; i < 8; i++) {
            float* row = cb + (tk*8 + i)*128 + td*8;
            #pragma unroll
            for (int j = 0; j < 4; j++) {
                float lo, hi;
                unpack2(acc[i][j], lo, hi);
                row[2*j] = lo; row[2*j + 1] = hi;
            }
        }
    }
    __syncthreads();
    if (team == 0) {
        #pragma unroll
        for (int i = 0; i < 8; i++) {
            const float* row = cb + (tk*8 + i)*128 + td*8;
            size_t grow = (size_t)b*128 + tk*8 + i;
            size_t base = which ? (grow*ADJ_N + (size_t)b*128 + td*8)
                                : ((size_t)ADJ_ELEMS + grow*DOUT + td*8);
            #pragma unroll
            for (int j = 0; j < 4; j++) {
                float lo, hi;
                unpack2(acc[i][j], lo, hi);
                out[base + 2*j]     = lo + row[2*j];
                out[base + 2*j + 1] = hi + row[2*j + 1];
            }
        }
    }
}

// ---------------- launch ----------------
extern "C" void kernel_launch(void* const* d_in, const int* in_sizes, int n_in,
                              void* d_out, int out_size) {
    const float* h    = (const float*)d_in[0];
    const int*   esrc = (const int*)d_in[1];
    const int*   edst = (const int*)d_in[2];
    const float* Wf   = (const float*)d_in[3];
    const float* bf   = (const float*)d_in[4];
    const float* Wp   = (const float*)d_in[5];
    const float* bp   = (const float*)d_in[6];
    float* out = (float*)d_out;

    static cudaStream_t s_side = nullptr;
    static cudaEvent_t  e_fork = nullptr, e_build = nullptr, e_join = nullptr;
    static bool attr_done = false;
    if (!s_side) {
        cudaStreamCreateWithFlags(&s_side, cudaStreamNonBlocking);
        cudaEventCreateWithFlags(&e_fork,  cudaEventDisableTiming);
        cudaEventCreateWithFlags(&e_build, cudaEventDisableTiming);
        cudaEventCreateWithFlags(&e_join,  cudaEventDisableTiming);
    }
    if (!attr_done) {
        cudaFuncSetAttribute(k_fuse, cudaFuncAttributeMaxDynamicSharedMemorySize, 131072);
        cudaFuncSetAttribute(k_as,   cudaFuncAttributeMaxDynamicSharedMemorySize, 65536);
        cudaFuncSetAttribute(k_pool, cudaFuncAttributeMaxDynamicSharedMemorySize, 131072);
        attr_done = true;
    }

    // side stream: edge-list build, then adj memset (overlaps prep+gemm)
    cudaEventRecord(e_fork, 0);
    cudaStreamWaitEvent(s_side, e_fork, 0);
    k_build<<<NB, 256, 0, s_side>>>(esrc, edst);
    cudaEventRecord(e_build, s_side);
    cudaMemsetAsync(d_out, 0, (size_t)ADJ_ELEMS * sizeof(float), s_side);
    cudaEventRecord(e_join, s_side);

    // main stream
    k_prep<<<8448, 256>>>(h, Wf, Wp);
    k_gemm_mma<<<dim3(128, 4), 256>>>();
    cudaStreamWaitEvent(0, e_build, 0);
    k_fuse<<<dim3(NB, 2), 1024, 131072>>>(bf, bp);
    k_as<<<dim3(NB, 2, 2), 1024, 65536>>>();
    cudaStreamWaitEvent(0, e_join, 0);
    k_pool<<<dim3(NB, 2), 512, 131072>>>(out);
}